// round 12
// baseline (speedup 1.0000x reference)
#include <cuda_runtime.h>
#include <math.h>

#define T_LEN    176400
#define NBATCH   16
#define NHARM    64
#define NBANDS   65
#define MAIN_NB  345          // ceil(176400/512), 2 samples/thread @256 thr
#define NORM_BPR 87           // 87*512 = 44544 >= 44100 float4 per row
#define PI_D 3.141592653589793115997963468544185161590576171875

typedef unsigned long long u64;

// Scratch (no allocations allowed). Transposed layout [batch][block]:
// norm's reduce reads are coalesced. Every slot overwritten by plain stores
// each call before being read -> no reset needed, replay-deterministic.
__device__ float g_partial[NBATCH * MAIN_NB];

// ---- packed f32x2 helpers (each lane = IEEE f32 RN, bit-identical to scalar)
__device__ __forceinline__ u64 pack2(float lo, float hi) {
    u64 v; asm("mov.b64 %0, {%1, %2};" : "=l"(v) : "f"(lo), "f"(hi)); return v;
}
__device__ __forceinline__ void unpack2(u64 v, float& lo, float& hi) {
    asm("mov.b64 {%0, %1}, %2;" : "=f"(lo), "=f"(hi) : "l"(v));
}
__device__ __forceinline__ u64 fmul2(u64 a, u64 b) {
    u64 d; asm("mul.rn.f32x2 %0, %1, %2;" : "=l"(d) : "l"(a), "l"(b)); return d;
}
__device__ __forceinline__ u64 fadd2(u64 a, u64 b) {
    u64 d; asm("add.rn.f32x2 %0, %1, %2;" : "=l"(d) : "l"(a), "l"(b)); return d;
}
__device__ __forceinline__ u64 ffma2(u64 a, u64 b, u64 c) {
    u64 d; asm("fma.rn.f32x2 %0, %1, %2, %3;"
               : "=l"(d) : "l"(a), "l"(b), "l"(c)); return d;
}

// ---------------------------------------------------------------------------
// Main kernel: 2 time samples per thread, all 16 batches, packed-f32x2
// mainloop. Range reduction packs {sample0, sample1}; accumulation packs
// batch pairs (b, b+1). Per-lane math identical to the scalar R9/R11 code:
//  n = RNE(arg/2pi) via 1.5*2^23 magic; 2-term Cody-Waite -> r in [-pi,pi];
//  __sinf(r) on MUFU (verified rel_err 2.6e-7).
// ---------------------------------------------------------------------------
__global__ void ddsp_main(
    const float* __restrict__ hd,      // (16, 64)
    const float* __restrict__ nbands,  // (16, 65)
    const float* __restrict__ adsr,    // (16, 4)
    const float* __restrict__ gain,    // (16, 1)
    const float* __restrict__ noise,   // (16, T)
    float* __restrict__ out)           // (16, T)
{
    __shared__ __align__(16) float sh_hd[NHARM * 16];  // transposed: [k][b]
    __shared__ u64 sh_ck2[NHARM];                      // {ck, ck} per k
    __shared__ float sh_par[NBATCH * 12];
    __shared__ unsigned int sh_max[NBATCH];

    int tid = threadIdx.x;
    for (int idx = tid; idx < NHARM * 16; idx += 256) {
        int k = idx >> 4, b = idx & 15;
        sh_hd[idx] = hd[b * NHARM + k];
    }
    if (tid < NHARM) {
        const float C32 = (float)(2.0 * PI_D * 440.0);   // fl32(2*pi*440)
        float ck = __fmul_rn(C32, (float)(tid + 1));     // bit-exact ref ck
        sh_ck2[tid] = pack2(ck, ck);
    }
    if (tid < NBATCH) {
        int b = tid;
        sh_max[b] = 0u;

        float s = 0.0f;
        for (int j = 0; j < NBANDS; j++) s += nbands[b * NBANDS + j];
        float nl = (s / (float)NBANDS) * 0.1f;

        float attack  = adsr[b * 4 + 0];
        float decay   = adsr[b * 4 + 1];
        float sus     = adsr[b * 4 + 2];
        float release = adsr[b * 4 + 3];

        int a  = (int)floorf(__fmul_rn(__fmul_rn(attack,  0.5f), 44100.0f)) + 1;
        int dd = (int)floorf(__fmul_rn(__fmul_rn(decay,   0.5f), 44100.0f)) + 1;
        int rr = (int)floorf(__fmul_rn(__fmul_rn(release, 0.5f), 44100.0f)) + 1;
        int total = a + dd + rr;
        if (total > T_LEN) {
            float scale = __fdiv_rn((float)T_LEN, (float)total);
            a  = (int)floorf(__fmul_rn((float)a,  scale));
            dd = (int)floorf(__fmul_rn((float)dd, scale));
            rr = (int)floorf(__fmul_rn((float)rr, scale));
        }
        int ss = T_LEN - (a + dd + rr);
        if (ss < 0) ss = 0;

        float af = (float)a, df = (float)dd, sf = (float)ss, rf = (float)rr;
        float* P = sh_par + b * 12;
        P[0] = af;
        P[1] = af + df;
        P[2] = af + df + sf;
        P[3] = 1.0f / fmaxf(af - 1.0f, 1.0f);
        P[4] = 1.0f / fmaxf(df - 1.0f, 1.0f);
        P[5] = 1.0f / fmaxf(rf - 1.0f, 1.0f);
        P[6] = sus;
        P[7] = gain[b];
        P[8] = nl;
    }
    __syncthreads();

    int i0 = blockIdx.x * 512 + tid;
    int i1 = i0 + 256;
    bool act0 = (i0 < T_LEN), act1 = (i1 < T_LEN);
    float fi0 = (float)i0, fi1 = (float)i1;
    const float DELTA = 4.0f / 176399.0f;         // compile-time IEEE f32
    float ti0 = __fmul_rn(fi0, DELTA);            // jax linspace: iota*delta
    float ti1 = __fmul_rn(fi1, DELTA);

    // packed constants (hoisted; both lanes identical)
    const float I2PI  = 0.15915494309189535f;
    const float MAGIC = 12582912.0f;                // 1.5 * 2^23
    const float C1N   = -6.28318548202514648437500f; // -fl32(2*pi)
    const float C2N   = 1.7484556000744625e-7f;     // -(2*pi - fl32(2*pi))
    u64 tiv    = pack2(ti0, ti1);
    u64 I2PIv  = pack2(I2PI, I2PI);
    u64 MAGICv = pack2(MAGIC, MAGIC);
    u64 NMAGv  = pack2(-MAGIC, -MAGIC);
    u64 C1Nv   = pack2(C1N, C1N);
    u64 C2Nv   = pack2(C2N, C2N);

    // accumulators: batch pairs (2b, 2b+1); acc0 = sample0, acc1 = sample1
    u64 acc0[8], acc1[8];
#pragma unroll
    for (int p = 0; p < 8; p++) { acc0[p] = 0ull; acc1[p] = 0ull; }

#pragma unroll 4
    for (int k = 0; k < NHARM; k++) {
        u64 ckv  = sh_ck2[k];                 // {ck, ck}, broadcast LDS.64
        u64 argv = fmul2(ckv, tiv);           // {fl32(ck*ti0), fl32(ck*ti1)}
        u64 t    = ffma2(argv, I2PIv, MAGICv);
        u64 nf   = fadd2(t, NMAGv);           // RNE(arg/2pi) per lane
        u64 r    = ffma2(nf, C1Nv, argv);
        r        = ffma2(nf, C2Nv, r);        // r in ~[-pi, pi]
        float r0, r1; unpack2(r, r0, r1);
        float s0 = __sinf(r0);                // MUFU pipe
        float s1 = __sinf(r1);
        u64 sv0 = pack2(s0, s0);
        u64 sv1 = pack2(s1, s1);

        const ulonglong2* hp = (const ulonglong2*)(sh_hd + k * 16);
        ulonglong2 ha = hp[0], hb = hp[1], hc = hp[2], hd4 = hp[3];
        acc0[0] = ffma2(ha.x,  sv0, acc0[0]);  acc1[0] = ffma2(ha.x,  sv1, acc1[0]);
        acc0[1] = ffma2(ha.y,  sv0, acc0[1]);  acc1[1] = ffma2(ha.y,  sv1, acc1[1]);
        acc0[2] = ffma2(hb.x,  sv0, acc0[2]);  acc1[2] = ffma2(hb.x,  sv1, acc1[2]);
        acc0[3] = ffma2(hb.y,  sv0, acc0[3]);  acc1[3] = ffma2(hb.y,  sv1, acc1[3]);
        acc0[4] = ffma2(hc.x,  sv0, acc0[4]);  acc1[4] = ffma2(hc.x,  sv1, acc1[4]);
        acc0[5] = ffma2(hc.y,  sv0, acc0[5]);  acc1[5] = ffma2(hc.y,  sv1, acc1[5]);
        acc0[6] = ffma2(hd4.x, sv0, acc0[6]);  acc1[6] = ffma2(hd4.x, sv1, acc1[6]);
        acc0[7] = ffma2(hd4.y, sv0, acc0[7]);  acc1[7] = ffma2(hd4.y, sv1, acc1[7]);
    }

    // unpack accumulators to scalars for the epilogue
    float a0[16], a1[16];
#pragma unroll
    for (int p = 0; p < 8; p++) {
        unpack2(acc0[p], a0[2 * p], a0[2 * p + 1]);
        unpack2(acc1[p], a1[2 * p], a1[2 * p + 1]);
    }

    const unsigned full = 0xFFFFFFFFu;
#pragma unroll
    for (int b = 0; b < 16; b++) {
        const float* P = sh_par + b * 12;
        float af = P[0], afd = P[1], ads = P[2];
        float ida = P[3], idd = P[4], idr = P[5];
        float sus = P[6], gn = P[7], nl = P[8];

        float env0;
        if (fi0 < af)       env0 = fi0 * ida;
        else if (fi0 < afd) env0 = 1.0f + ((sus - 1.0f) * (fi0 - af)) * idd;
        else if (fi0 < ads) env0 = sus;
        else                env0 = sus * (1.0f - (fi0 - ads) * idr);
        float env1;
        if (fi1 < af)       env1 = fi1 * ida;
        else if (fi1 < afd) env1 = 1.0f + ((sus - 1.0f) * (fi1 - af)) * idd;
        else if (fi1 < ads) env1 = sus;
        else                env1 = sus * (1.0f - (fi1 - ads) * idr);

        float nz0 = act0 ? noise[b * T_LEN + i0] : 0.0f;
        float nz1 = act1 ? noise[b * T_LEN + i1] : 0.0f;
        float sig0 = ((a0[b] + fmaf(nz0, 2.0f, -1.0f) * nl) * env0) * gn;
        float sig1 = ((a1[b] + fmaf(nz1, 2.0f, -1.0f) * nl) * env1) * gn;
        if (!act0) sig0 = 0.0f;
        if (!act1) sig1 = 0.0f;
        if (act0) out[b * T_LEN + i0] = sig0;
        if (act1) out[b * T_LEN + i1] = sig1;

        float am = fmaxf(fabsf(sig0), fabsf(sig1));   // one tree for 2 samples
#pragma unroll
        for (int off = 16; off; off >>= 1)
            am = fmaxf(am, __shfl_xor_sync(full, am, off));
        if ((tid & 31) == 0) atomicMax(&sh_max[b], __float_as_uint(am));
    }
    __syncthreads();
    // plain stores — transposed [batch][block] slots, overwritten every call
    if (tid < NBATCH)
        g_partial[tid * MAIN_NB + blockIdx.x] = __uint_as_float(sh_max[tid]);
}

// ---------------------------------------------------------------------------
// Norm kernel: block (x, b) redundantly reduces batch b's 345 contiguous
// partials (L2-resident, coalesced), then scales its 2-float4 chunk of row b.
// No atomics, no inter-block sync, nothing to reset.
// ---------------------------------------------------------------------------
__global__ void __launch_bounds__(256) ddsp_norm(float4* __restrict__ out) {
    __shared__ float sh_wmax[8];
    __shared__ float sh_inv;
    const int T4 = T_LEN / 4;                 // 44100 float4 per row
    int b = blockIdx.y;
    int tid = threadIdx.x;

    const float* part = g_partial + b * MAIN_NB;
    float m = 0.0f;
    for (int j = tid; j < MAIN_NB; j += 256)
        m = fmaxf(m, part[j]);
    const unsigned full = 0xFFFFFFFFu;
#pragma unroll
    for (int off = 16; off; off >>= 1)
        m = fmaxf(m, __shfl_xor_sync(full, m, off));
    if ((tid & 31) == 0) sh_wmax[tid >> 5] = m;
    __syncthreads();
    if (tid == 0) {
        float mm = sh_wmax[0];
#pragma unroll
        for (int w = 1; w < 8; w++) mm = fmaxf(mm, sh_wmax[w]);
        sh_inv = 1.0f / (mm + 1e-5f);
    }
    __syncthreads();
    float inv = sh_inv;

    float4* row = out + (size_t)b * T4;
    int i0 = blockIdx.x * 512 + tid;
    int i1 = i0 + 256;
    bool a0 = (i0 < T4), a1 = (i1 < T4);
    float4 v0, v1;
    if (a0) v0 = row[i0];
    if (a1) v1 = row[i1];
    if (a0) {
        v0.x *= inv; v0.y *= inv; v0.z *= inv; v0.w *= inv;
        row[i0] = v0;
    }
    if (a1) {
        v1.x *= inv; v1.y *= inv; v1.z *= inv; v1.w *= inv;
        row[i1] = v1;
    }
}

extern "C" void kernel_launch(void* const* d_in, const int* in_sizes, int n_in,
                              void* d_out, int out_size) {
    // input order: base_audio, harmonic_dist, noise_bands, adsr, gain, noise
    const float* hd     = (const float*)d_in[1];
    const float* nbands = (const float*)d_in[2];
    const float* adsr   = (const float*)d_in[3];
    const float* gain   = (const float*)d_in[4];
    const float* noise  = (const float*)d_in[5];
    float* out = (float*)d_out;

    ddsp_main<<<MAIN_NB, 256>>>(hd, nbands, adsr, gain, noise, out);
    ddsp_norm<<<dim3(NORM_BPR, NBATCH), 256>>>((float4*)out);
}

// round 13
// speedup vs baseline: 1.4294x; 1.4294x over previous
#include <cuda_runtime.h>
#include <math.h>

#define T_LEN    176400
#define NBATCH   16
#define NBH      8            // batches per thread (half)
#define NHARM    64
#define NBANDS   65
#define MAIN_NB  690          // ceil(176400/256); grid = (690, 2)
#define NORM_BPR 87           // 87*512 = 44544 >= 44100 float4 per row
#define PI_D 3.141592653589793115997963468544185161590576171875

// Scratch (no allocations allowed). Layout [batch][block]: norm's reduce
// reads are coalesced. Every slot overwritten by plain stores each call
// before being read -> no reset needed, replay-deterministic.
__device__ float g_partial[NBATCH * MAIN_NB];

// ---------------------------------------------------------------------------
// Range reduction, bit-exact w.r.t. the reference's f32 argument:
//  n = RNE(arg/2pi) via 1.5*2^23 magic; 2-term Cody-Waite -> r in [-pi,pi]
//  (4 fma-pipe ops), then __sinf(r) on the MUFU pipe (verified 2.6e-7).
// ---------------------------------------------------------------------------
__device__ __forceinline__ float sin_reduced(float a) {
    const float I2PI  = 0.15915494309189535f;
    const float MAGIC = 12582912.0f;                // 1.5 * 2^23
    const float C1    = 6.28318548202514648437500f; // fl32(2*pi)
    const float C2N   = 1.7484556000744625e-7f;     // -(2*pi - C1)
    float t  = fmaf(a, I2PI, MAGIC);
    float nf = t - MAGIC;                           // RNE(a/2pi), exact int
    float r  = fmaf(nf, -C1, a);
    r = fmaf(nf, C2N, r);                           // r in ~[-pi, pi]
    return __sinf(r);                               // MUFU pipe
}

// ---------------------------------------------------------------------------
// Main kernel: one thread = one time sample x 8 batches (blockIdx.y = half).
// Halves the accumulator/weight register pressure (~75 -> ~48 regs) to lift
// occupancy from ~6 to ~10 warps/SMSP; sin is computed redundantly (x2) on
// the underused MUFU pipe. Per-(b,i) arithmetic identical to R9/R11 ->
// rel_err must stay exactly 2.577372e-7.
// ---------------------------------------------------------------------------
__global__ void ddsp_main(
    const float* __restrict__ hd,      // (16, 64)
    const float* __restrict__ nbands,  // (16, 65)
    const float* __restrict__ adsr,    // (16, 4)
    const float* __restrict__ gain,    // (16, 1)
    const float* __restrict__ noise,   // (16, T)
    float* __restrict__ out)           // (16, T)
{
    __shared__ __align__(16) float sh_hd[NHARM * NBH];  // [k][j] for this half
    __shared__ float sh_ck[NHARM];
    __shared__ float sh_par[NBH * 12];
    __shared__ unsigned int sh_max[NBH];

    int tid = threadIdx.x;
    int bh  = blockIdx.y;              // 0 or 1: batches bh*8 .. bh*8+7

    for (int idx = tid; idx < NHARM * NBH; idx += 256) {
        int k = idx >> 3, j = idx & 7;
        sh_hd[idx] = hd[(bh * NBH + j) * NHARM + k];
    }
    if (tid < NHARM) {
        const float C32 = (float)(2.0 * PI_D * 440.0);   // fl32(2*pi*440)
        sh_ck[tid] = __fmul_rn(C32, (float)(tid + 1));   // bit-exact ref ck
    }
    if (tid < NBH) {
        int b = bh * NBH + tid;
        sh_max[tid] = 0u;

        float s = 0.0f;
        for (int j = 0; j < NBANDS; j++) s += nbands[b * NBANDS + j];
        float nl = (s / (float)NBANDS) * 0.1f;

        float attack  = adsr[b * 4 + 0];
        float decay   = adsr[b * 4 + 1];
        float sus     = adsr[b * 4 + 2];
        float release = adsr[b * 4 + 3];

        int a  = (int)floorf(__fmul_rn(__fmul_rn(attack,  0.5f), 44100.0f)) + 1;
        int dd = (int)floorf(__fmul_rn(__fmul_rn(decay,   0.5f), 44100.0f)) + 1;
        int rr = (int)floorf(__fmul_rn(__fmul_rn(release, 0.5f), 44100.0f)) + 1;
        int total = a + dd + rr;
        if (total > T_LEN) {
            float scale = __fdiv_rn((float)T_LEN, (float)total);
            a  = (int)floorf(__fmul_rn((float)a,  scale));
            dd = (int)floorf(__fmul_rn((float)dd, scale));
            rr = (int)floorf(__fmul_rn((float)rr, scale));
        }
        int ss = T_LEN - (a + dd + rr);
        if (ss < 0) ss = 0;

        float af = (float)a, df = (float)dd, sf = (float)ss, rf = (float)rr;
        float* P = sh_par + tid * 12;
        P[0] = af;
        P[1] = af + df;
        P[2] = af + df + sf;
        P[3] = 1.0f / fmaxf(af - 1.0f, 1.0f);
        P[4] = 1.0f / fmaxf(df - 1.0f, 1.0f);
        P[5] = 1.0f / fmaxf(rf - 1.0f, 1.0f);
        P[6] = sus;
        P[7] = gain[b];
        P[8] = nl;
    }
    __syncthreads();

    int i = blockIdx.x * 256 + tid;
    bool act = (i < T_LEN);
    float fi = (float)i;
    const float DELTA = 4.0f / 176399.0f;         // compile-time IEEE f32
    float ti = __fmul_rn(fi, DELTA);              // jax linspace: iota*delta

    float acc[NBH];
#pragma unroll
    for (int j = 0; j < NBH; j++) acc[j] = 0.0f;

#pragma unroll 4
    for (int k = 0; k < NHARM; k++) {
        float sv = sin_reduced(__fmul_rn(sh_ck[k], ti)); // ref f32 rounding
        const float4* hp = (const float4*)(sh_hd + k * NBH);
        float4 h0 = hp[0], h1 = hp[1];
        acc[0] = fmaf(h0.x, sv, acc[0]);  acc[1] = fmaf(h0.y, sv, acc[1]);
        acc[2] = fmaf(h0.z, sv, acc[2]);  acc[3] = fmaf(h0.w, sv, acc[3]);
        acc[4] = fmaf(h1.x, sv, acc[4]);  acc[5] = fmaf(h1.y, sv, acc[5]);
        acc[6] = fmaf(h1.z, sv, acc[6]);  acc[7] = fmaf(h1.w, sv, acc[7]);
    }

    const unsigned full = 0xFFFFFFFFu;
#pragma unroll
    for (int j = 0; j < NBH; j++) {
        int b = bh * NBH + j;
        const float* P = sh_par + j * 12;
        float af = P[0], afd = P[1], ads = P[2];
        float ida = P[3], idd = P[4], idr = P[5];
        float sus = P[6], gn = P[7], nl = P[8];

        float env;
        if (fi < af)       env = fi * ida;
        else if (fi < afd) env = 1.0f + ((sus - 1.0f) * (fi - af)) * idd;
        else if (fi < ads) env = sus;
        else               env = sus * (1.0f - (fi - ads) * idr);

        float nz = act ? noise[b * T_LEN + i] : 0.0f;
        float nn = fmaf(nz, 2.0f, -1.0f) * nl;
        float sig = ((acc[j] + nn) * env) * gn;
        if (!act) sig = 0.0f;
        if (act) out[b * T_LEN + i] = sig;

        float am = fabsf(sig);
#pragma unroll
        for (int off = 16; off; off >>= 1)
            am = fmaxf(am, __shfl_xor_sync(full, am, off));
        if ((tid & 31) == 0) atomicMax(&sh_max[j], __float_as_uint(am));
    }
    __syncthreads();
    // plain stores — [batch][block] slots, overwritten every call
    if (tid < NBH)
        g_partial[(bh * NBH + tid) * MAIN_NB + blockIdx.x] =
            __uint_as_float(sh_max[tid]);
}

// ---------------------------------------------------------------------------
// Norm kernel: block (x, b) redundantly reduces batch b's 690 contiguous
// partials (L2-resident, coalesced), then scales its 2-float4 chunk of row b.
// No atomics, no inter-block sync, nothing to reset.
// ---------------------------------------------------------------------------
__global__ void __launch_bounds__(256) ddsp_norm(float4* __restrict__ out) {
    __shared__ float sh_wmax[8];
    __shared__ float sh_inv;
    const int T4 = T_LEN / 4;                 // 44100 float4 per row
    int b = blockIdx.y;
    int tid = threadIdx.x;

    const float* part = g_partial + b * MAIN_NB;
    float m = 0.0f;
    for (int j = tid; j < MAIN_NB; j += 256)
        m = fmaxf(m, part[j]);
    const unsigned full = 0xFFFFFFFFu;
#pragma unroll
    for (int off = 16; off; off >>= 1)
        m = fmaxf(m, __shfl_xor_sync(full, m, off));
    if ((tid & 31) == 0) sh_wmax[tid >> 5] = m;
    __syncthreads();
    if (tid == 0) {
        float mm = sh_wmax[0];
#pragma unroll
        for (int w = 1; w < 8; w++) mm = fmaxf(mm, sh_wmax[w]);
        sh_inv = 1.0f / (mm + 1e-5f);
    }
    __syncthreads();
    float inv = sh_inv;

    float4* row = out + (size_t)b * T4;
    int i0 = blockIdx.x * 512 + tid;
    int i1 = i0 + 256;
    bool a0 = (i0 < T4), a1 = (i1 < T4);
    float4 v0, v1;
    if (a0) v0 = row[i0];
    if (a1) v1 = row[i1];
    if (a0) {
        v0.x *= inv; v0.y *= inv; v0.z *= inv; v0.w *= inv;
        row[i0] = v0;
    }
    if (a1) {
        v1.x *= inv; v1.y *= inv; v1.z *= inv; v1.w *= inv;
        row[i1] = v1;
    }
}

extern "C" void kernel_launch(void* const* d_in, const int* in_sizes, int n_in,
                              void* d_out, int out_size) {
    // input order: base_audio, harmonic_dist, noise_bands, adsr, gain, noise
    const float* hd     = (const float*)d_in[1];
    const float* nbands = (const float*)d_in[2];
    const float* adsr   = (const float*)d_in[3];
    const float* gain   = (const float*)d_in[4];
    const float* noise  = (const float*)d_in[5];
    float* out = (float*)d_out;

    ddsp_main<<<dim3(MAIN_NB, 2), 256>>>(hd, nbands, adsr, gain, noise, out);
    ddsp_norm<<<dim3(NORM_BPR, NBATCH), 256>>>((float4*)out);
}

// round 14
// speedup vs baseline: 1.5122x; 1.0579x over previous
#include <cuda_runtime.h>
#include <math.h>

#define T_LEN    176400
#define NBATCH   16
#define NBH      8            // batches per thread (half)
#define NHARM    64
#define NBANDS   65
#define MAIN_NB  690          // ceil(176400/256); grid = (690, 2)
#define NORM_BPR 87           // 87*512 = 44544 >= 44100 float4 per row
#define PI_D 3.141592653589793115997963468544185161590576171875

// Scratch (no allocations allowed). Layout [batch][block]: norm's reduce
// reads are coalesced. Every slot overwritten by plain stores each call
// before being read -> no reset needed, replay-deterministic.
__device__ float g_partial[NBATCH * MAIN_NB];

// ---------------------------------------------------------------------------
// Range reduction, bit-exact w.r.t. the reference's f32 argument:
//  n = RNE(arg/2pi) via 1.5*2^23 magic; 2-term Cody-Waite -> r in [-pi,pi]
//  (4 fma-pipe ops), then __sinf(r) on the MUFU pipe (verified 2.6e-7).
// ---------------------------------------------------------------------------
__device__ __forceinline__ float sin_reduced(float a) {
    const float I2PI  = 0.15915494309189535f;
    const float MAGIC = 12582912.0f;                // 1.5 * 2^23
    const float C1    = 6.28318548202514648437500f; // fl32(2*pi)
    const float C2N   = 1.7484556000744625e-7f;     // -(2*pi - C1)
    float t  = fmaf(a, I2PI, MAGIC);
    float nf = t - MAGIC;                           // RNE(a/2pi), exact int
    float r  = fmaf(nf, -C1, a);
    r = fmaf(nf, C2N, r);                           // r in ~[-pi, pi]
    return __sinf(r);                               // MUFU pipe
}

// ---------------------------------------------------------------------------
// Main kernel: one thread = one time sample x 8 batches (blockIdx.y = half).
// R14 changes vs R13 (mainloop math untouched):
//  - noise values prefetched into regs BEFORE the mainloop (LDG latency
//    hidden under ~15us of compute; removes end-of-kernel exposed stalls)
//  - per-batch max via one REDUX.MAX (__reduce_max_sync on uint-punned
//    nonneg floats; order-isomorphic) instead of 5-shfl butterfly
//  - k-loop unroll 8
// ---------------------------------------------------------------------------
__global__ void ddsp_main(
    const float* __restrict__ hd,      // (16, 64)
    const float* __restrict__ nbands,  // (16, 65)
    const float* __restrict__ adsr,    // (16, 4)
    const float* __restrict__ gain,    // (16, 1)
    const float* __restrict__ noise,   // (16, T)
    float* __restrict__ out)           // (16, T)
{
    __shared__ __align__(16) float sh_hd[NHARM * NBH];  // [k][j] for this half
    __shared__ float sh_ck[NHARM];
    __shared__ float sh_par[NBH * 12];
    __shared__ unsigned int sh_max[NBH];

    int tid = threadIdx.x;
    int bh  = blockIdx.y;              // 0 or 1: batches bh*8 .. bh*8+7

    for (int idx = tid; idx < NHARM * NBH; idx += 256) {
        int k = idx >> 3, j = idx & 7;
        sh_hd[idx] = hd[(bh * NBH + j) * NHARM + k];
    }
    if (tid < NHARM) {
        const float C32 = (float)(2.0 * PI_D * 440.0);   // fl32(2*pi*440)
        sh_ck[tid] = __fmul_rn(C32, (float)(tid + 1));   // bit-exact ref ck
    }
    if (tid < NBH) {
        int b = bh * NBH + tid;
        sh_max[tid] = 0u;

        float s = 0.0f;
        for (int j = 0; j < NBANDS; j++) s += nbands[b * NBANDS + j];
        float nl = (s / (float)NBANDS) * 0.1f;

        float attack  = adsr[b * 4 + 0];
        float decay   = adsr[b * 4 + 1];
        float sus     = adsr[b * 4 + 2];
        float release = adsr[b * 4 + 3];

        int a  = (int)floorf(__fmul_rn(__fmul_rn(attack,  0.5f), 44100.0f)) + 1;
        int dd = (int)floorf(__fmul_rn(__fmul_rn(decay,   0.5f), 44100.0f)) + 1;
        int rr = (int)floorf(__fmul_rn(__fmul_rn(release, 0.5f), 44100.0f)) + 1;
        int total = a + dd + rr;
        if (total > T_LEN) {
            float scale = __fdiv_rn((float)T_LEN, (float)total);
            a  = (int)floorf(__fmul_rn((float)a,  scale));
            dd = (int)floorf(__fmul_rn((float)dd, scale));
            rr = (int)floorf(__fmul_rn((float)rr, scale));
        }
        int ss = T_LEN - (a + dd + rr);
        if (ss < 0) ss = 0;

        float af = (float)a, df = (float)dd, sf = (float)ss, rf = (float)rr;
        float* P = sh_par + tid * 12;
        P[0] = af;
        P[1] = af + df;
        P[2] = af + df + sf;
        P[3] = 1.0f / fmaxf(af - 1.0f, 1.0f);
        P[4] = 1.0f / fmaxf(df - 1.0f, 1.0f);
        P[5] = 1.0f / fmaxf(rf - 1.0f, 1.0f);
        P[6] = sus;
        P[7] = gain[b];
        P[8] = nl;
    }
    __syncthreads();

    int i = blockIdx.x * 256 + tid;
    bool act = (i < T_LEN);
    float fi = (float)i;
    const float DELTA = 4.0f / 176399.0f;         // compile-time IEEE f32
    float ti = __fmul_rn(fi, DELTA);              // jax linspace: iota*delta

    // ---- noise prefetch: issue all 8 LDGs now; consumed after the mainloop
    float nz[NBH];
#pragma unroll
    for (int j = 0; j < NBH; j++) {
        int b = bh * NBH + j;
        nz[j] = act ? noise[b * T_LEN + i] : 0.0f;
    }

    float acc[NBH];
#pragma unroll
    for (int j = 0; j < NBH; j++) acc[j] = 0.0f;

#pragma unroll 8
    for (int k = 0; k < NHARM; k++) {
        float sv = sin_reduced(__fmul_rn(sh_ck[k], ti)); // ref f32 rounding
        const float4* hp = (const float4*)(sh_hd + k * NBH);
        float4 h0 = hp[0], h1 = hp[1];
        acc[0] = fmaf(h0.x, sv, acc[0]);  acc[1] = fmaf(h0.y, sv, acc[1]);
        acc[2] = fmaf(h0.z, sv, acc[2]);  acc[3] = fmaf(h0.w, sv, acc[3]);
        acc[4] = fmaf(h1.x, sv, acc[4]);  acc[5] = fmaf(h1.y, sv, acc[5]);
        acc[6] = fmaf(h1.z, sv, acc[6]);  acc[7] = fmaf(h1.w, sv, acc[7]);
    }

#pragma unroll
    for (int j = 0; j < NBH; j++) {
        int b = bh * NBH + j;
        const float* P = sh_par + j * 12;
        float af = P[0], afd = P[1], ads = P[2];
        float ida = P[3], idd = P[4], idr = P[5];
        float sus = P[6], gn = P[7], nl = P[8];

        float env;
        if (fi < af)       env = fi * ida;
        else if (fi < afd) env = 1.0f + ((sus - 1.0f) * (fi - af)) * idd;
        else if (fi < ads) env = sus;
        else               env = sus * (1.0f - (fi - ads) * idr);

        float nn = fmaf(nz[j], 2.0f, -1.0f) * nl;
        float sig = ((acc[j] + nn) * env) * gn;
        if (!act) sig = 0.0f;
        if (act) out[b * T_LEN + i] = sig;

        // one REDUX.MAX replaces the 5-shfl butterfly (nonneg -> uint order)
        unsigned int mu = __reduce_max_sync(0xFFFFFFFFu,
                                            __float_as_uint(fabsf(sig)));
        if ((tid & 31) == 0) atomicMax(&sh_max[j], mu);
    }
    __syncthreads();
    // plain stores — [batch][block] slots, overwritten every call
    if (tid < NBH)
        g_partial[(bh * NBH + tid) * MAIN_NB + blockIdx.x] =
            __uint_as_float(sh_max[tid]);
}

// ---------------------------------------------------------------------------
// Norm kernel: block (x, b) redundantly reduces batch b's 690 contiguous
// partials (L2-resident, coalesced), then scales its 2-float4 chunk of row b.
// No atomics, no inter-block sync, nothing to reset.
// ---------------------------------------------------------------------------
__global__ void __launch_bounds__(256) ddsp_norm(float4* __restrict__ out) {
    __shared__ float sh_wmax[8];
    __shared__ float sh_inv;
    const int T4 = T_LEN / 4;                 // 44100 float4 per row
    int b = blockIdx.y;
    int tid = threadIdx.x;

    const float* part = g_partial + b * MAIN_NB;
    float m = 0.0f;
    for (int j = tid; j < MAIN_NB; j += 256)
        m = fmaxf(m, part[j]);
    unsigned int mu = __reduce_max_sync(0xFFFFFFFFu, __float_as_uint(m));
    if ((tid & 31) == 0) sh_wmax[tid >> 5] = __uint_as_float(mu);
    __syncthreads();
    if (tid == 0) {
        float mm = sh_wmax[0];
#pragma unroll
        for (int w = 1; w < 8; w++) mm = fmaxf(mm, sh_wmax[w]);
        sh_inv = 1.0f / (mm + 1e-5f);
    }
    __syncthreads();
    float inv = sh_inv;

    float4* row = out + (size_t)b * T4;
    int i0 = blockIdx.x * 512 + tid;
    int i1 = i0 + 256;
    bool a0 = (i0 < T4), a1 = (i1 < T4);
    float4 v0, v1;
    if (a0) v0 = row[i0];
    if (a1) v1 = row[i1];
    if (a0) {
        v0.x *= inv; v0.y *= inv; v0.z *= inv; v0.w *= inv;
        row[i0] = v0;
    }
    if (a1) {
        v1.x *= inv; v1.y *= inv; v1.z *= inv; v1.w *= inv;
        row[i1] = v1;
    }
}

extern "C" void kernel_launch(void* const* d_in, const int* in_sizes, int n_in,
                              void* d_out, int out_size) {
    // input order: base_audio, harmonic_dist, noise_bands, adsr, gain, noise
    const float* hd     = (const float*)d_in[1];
    const float* nbands = (const float*)d_in[2];
    const float* adsr   = (const float*)d_in[3];
    const float* gain   = (const float*)d_in[4];
    const float* noise  = (const float*)d_in[5];
    float* out = (float*)d_out;

    ddsp_main<<<dim3(MAIN_NB, 2), 256>>>(hd, nbands, adsr, gain, noise, out);
    ddsp_norm<<<dim3(NORM_BPR, NBATCH), 256>>>((float4*)out);
}